// round 7
// baseline (speedup 1.0000x reference)
#include <cuda_runtime.h>
#include <cuda_bf16.h>
#include <math.h>

#define NIMG   4
#define NPROP  2000
#define MAXGT  64
#define HH     512
#define WW     512
#define PPOS   66
#define NNEG   134
#define NROIS  200
#define MH     28
#define MW     28
#define EPSF   1e-8f
#define NWORDS (NPROP / 4)        // 500 packed flag words per image

// Output layout (float32, concatenated flattened tuple):
//   rois    [4][200][4]     @ 0      (3200)
//   class   [4][200]        @ 3200   (800)
//   deltas  [4][200][4]     @ 4000   (3200)
//   masks   [4][200][28][28]@ 7200   (627200)
#define OFF_ROIS  0
#define OFF_CLS   3200
#define OFF_DEL   4000
#define OFF_MSK   7200

// XLA rewrites x / const into x * (1/const) (algebraic simplifier).
// Reproduce bit-exactly: these fold at compile time to the same f32 XLA uses.
#define RCP_033  (1.0f / 0.33f)   // 66*r rounds to exactly 200.0f (division gives 199.99998)
#define RCP_01   (1.0f / 0.1f)    // exactly 10.0f
#define RCP_02   (1.0f / 0.2f)    // exactly 5.0f
#define RCP_27   (1.0f / 27.0f)

// ---------------- device scratch (no allocations allowed) ----------------
__device__ int            g_best[NIMG][NPROP];
__device__ unsigned char  g_posf[NIMG][NPROP];   // 0/1 bytes, NPROP%4==0
__device__ unsigned char  g_negf[NIMG][NPROP];

// ---------------- mask dtype probe (warp-collective, into smem) ----------------
// Mask values are only 0/1, so the byte stream discriminates the dtype:
//   any byte > 1                -> float32 or bf16
//     nonzero byte at p%4==1    -> bf16 (f32 0/1 has zero there)
//   else: byte==1 at p%4!=0     -> uint8/bool
//   else                        -> int32
__device__ __forceinline__ void probe_mask_fmt(const unsigned char* __restrict__ m,
                                               int lane, int* s_fmt) {
    int a = 0, b = 0, c = 0;
    for (int p = lane; p < 4096; p += 32) {
        unsigned char v = __ldg(m + p);
        if (v > 1) a = 1;
        if ((p & 3) == 1 && v != 0) b = 1;
        if ((p & 3) != 0 && v == 1) c = 1;
    }
    unsigned am = __ballot_sync(0xFFFFFFFFu, a);
    unsigned bm = __ballot_sync(0xFFFFFFFFu, b);
    unsigned cm = __ballot_sync(0xFFFFFFFFu, c);
    if (lane == 0) {
        int fmt;
        if (am) fmt = bm ? 3 : 2;
        else    fmt = cm ? 0 : 1;
        *s_fmt = fmt;
    }
}

__device__ __forceinline__ float mask_at(const void* m, int fmt, int idx) {
    switch (fmt) {
        case 0:  return (float)__ldg((const unsigned char*)m + idx);
        case 1:  return (float)__ldg((const int*)m + idx);
        case 3: {
            unsigned short u = __ldg((const unsigned short*)m + idx);
            __nv_bfloat16 v;
            *(unsigned short*)&v = u;
            return __bfloat162float(v);
        }
        default: return __ldg((const float*)m + idx);
    }
}

// ---------------- IoU / flags: one WARP per proposal ----------------
__global__ void __launch_bounds__(256)
k_iou(const float* __restrict__ props,
      const int*   __restrict__ ids,
      const float* __restrict__ gtb) {
    const int img  = blockIdx.y;
    const int wid  = threadIdx.x >> 5;
    const int lane = threadIdx.x & 31;
    const int prop = blockIdx.x * 8 + wid;   // 250*8 = 2000

    __shared__ float4 sgt[MAXGT];
    __shared__ int    sfl[MAXGT];   // bit0: gt_valid, bit1: crowd
    if (threadIdx.x < MAXGT) {
        const float* g = gtb + (img * MAXGT + threadIdx.x) * 4;
        float4 b; b.x = g[0]; b.y = g[1]; b.z = g[2]; b.w = g[3];
        sgt[threadIdx.x] = b;
        int id = ids[img * MAXGT + threadIdx.x];
        bool bv = (b.x != 0.f) || (b.y != 0.f) || (b.z != 0.f) || (b.w != 0.f);
        sfl[threadIdx.x] = ((bv && id > 0) ? 1 : 0) | ((bv && id < 0) ? 2 : 0);
    }
    __syncthreads();

    const float4 p = *(const float4*)(props + (img * NPROP + prop) * 4);
    const float py1 = p.x, px1 = p.y, py2 = p.z, px2 = p.w;
    const bool prop_valid = (py1 != 0.f) || (px1 != 0.f) || (py2 != 0.f) || (px2 != 0.f);
    const float a1 = __fmul_rn(__fsub_rn(py2, py1), __fsub_rn(px2, px1));

    float best = -INFINITY; int bi = 0;
    float crowd_max = -1.0f;
    #pragma unroll
    for (int t = 0; t < 2; ++t) {
        const int j = lane + 32 * t;
        float4 g = sgt[j];
        int fl = sfl[j];
        float ih = fmaxf(__fsub_rn(fminf(py2, g.z), fmaxf(py1, g.x)), 0.0f);
        float iw = fmaxf(__fsub_rn(fminf(px2, g.w), fmaxf(px1, g.y)), 0.0f);
        float inter = __fmul_rn(ih, iw);
        float a2 = __fmul_rn(__fsub_rn(g.z, g.x), __fsub_rn(g.w, g.y));
        float denom = __fadd_rn(__fsub_rn(__fadd_rn(a1, a2), inter), EPSF);
        float iou = __fdiv_rn(inter, denom);
        float ov = (fl & 1) ? iou : -1.0f;
        if (ov > best) { best = ov; bi = j; }   // j < j+32: first-max kept
        float cv = (fl & 2) ? iou : -1.0f;
        crowd_max = fmaxf(crowd_max, cv);
    }

    // Butterfly reduce: (max value, lowest index among maxima) + crowd max.
    #pragma unroll
    for (int off = 16; off > 0; off >>= 1) {
        float ob = __shfl_xor_sync(0xFFFFFFFFu, best, off);
        int   oi = __shfl_xor_sync(0xFFFFFFFFu, bi, off);
        float oc = __shfl_xor_sync(0xFFFFFFFFu, crowd_max, off);
        if (ob > best || (ob == best && oi < bi)) { best = ob; bi = oi; }
        crowd_max = fmaxf(crowd_max, oc);
    }

    if (lane == 0) {
        bool pos = (best >= 0.5f) && prop_valid;
        bool neg = (best < 0.5f) && (crowd_max < 0.001f) && prop_valid && !pos;
        g_best[img][prop] = bi;
        g_posf[img][prop] = pos ? 1 : 0;
        g_negf[img][prop] = neg ? 1 : 0;
    }
}

// ---- fused: per-block selection scan + roi/cls/delta emit + mask row ----
// Grid (NROIS, NIMG), 784 threads. Warp 0 redoes the (cheap) stable first-k
// compaction from the packed flag bytes; warp 1 probes the mask dtype; then
// thread 0 emits row k's roi/class/deltas and all threads do row k's mask.
// Chunk compaction: lane owns 16 contiguous words (64 proposals); counts,
// 5-step shuffle exclusive-prefix, rewalk writing ranked indices. Stable by
// construction (ascending chunks, ascending bytes within word).
__global__ void __launch_bounds__(784, 2)
k_emit_masks(const float* __restrict__ props,
             const int*   __restrict__ ids,
             const float* __restrict__ gtb,
             const void*  __restrict__ masks,
             float* __restrict__ out) {
    const int img = blockIdx.y;
    const int k   = blockIdx.x;      // 0..199 (roi row / mask row)

    __shared__ int s_pos_idx[PPOS];
    __shared__ int s_neg_idx[NNEG];
    __shared__ int s_pos_count, s_neg_count, s_fmt;

    if (threadIdx.x < 32) {
        const int lane = threadIdx.x;
        const unsigned* pw = (const unsigned*)&g_posf[img][0];  // 500 words
        const unsigned* nw = (const unsigned*)&g_negf[img][0];
        const int base = lane * 16;
        int cp = 0, cn = 0;
        #pragma unroll
        for (int t = 0; t < 16; ++t) {
            const int widx = base + t;
            unsigned a = (widx < NWORDS) ? __ldg(pw + widx) : 0u;
            unsigned b = (widx < NWORDS) ? __ldg(nw + widx) : 0u;
            cp += __popc(a);
            cn += __popc(b);
        }
        // inclusive prefix -> exclusive base + totals
        int pinc = cp, ninc = cn;
        #pragma unroll
        for (int off = 1; off < 32; off <<= 1) {
            int up = __shfl_up_sync(0xFFFFFFFFu, pinc, off);
            int un = __shfl_up_sync(0xFFFFFFFFu, ninc, off);
            if (lane >= off) { pinc += up; ninc += un; }
        }
        const int ptot = __shfl_sync(0xFFFFFFFFu, pinc, 31);
        const int ntot = __shfl_sync(0xFFFFFFFFu, ninc, 31);
        int pr = pinc - cp;   // exclusive rank base for this lane's chunk
        int nr = ninc - cn;
        if (cp > 0 && pr < PPOS) {
            for (int t = 0; t < 16; ++t) {
                const int widx = base + t;
                unsigned w = (widx < NWORDS) ? __ldg(pw + widx) : 0u;
                if (!w) continue;
                #pragma unroll
                for (int b = 0; b < 4; ++b)
                    if ((w >> (8 * b)) & 1u) {
                        if (pr < PPOS) s_pos_idx[pr] = widx * 4 + b;
                        pr++;
                    }
            }
        }
        if (cn > 0 && nr < NNEG) {
            for (int t = 0; t < 16; ++t) {
                const int widx = base + t;
                unsigned w = (widx < NWORDS) ? __ldg(nw + widx) : 0u;
                if (!w) continue;
                #pragma unroll
                for (int b = 0; b < 4; ++b)
                    if ((w >> (8 * b)) & 1u) {
                        if (nr < NNEG) s_neg_idx[nr] = widx * 4 + b;
                        nr++;
                    }
            }
        }
        if (lane == 0) {
            int pos_count = ptot < PPOS ? ptot : PPOS;
            int neg_target = (int)(__fmul_rn((float)pos_count, RCP_033)) - pos_count;
            int avail = ntot < NNEG ? ntot : NNEG;
            s_pos_count = pos_count;
            s_neg_count = neg_target < 0 ? 0 : (neg_target < avail ? neg_target : avail);
        }
    } else if (threadIdx.x < 64) {
        probe_mask_fmt((const unsigned char*)masks, threadIdx.x - 32, &s_fmt);
    }
    __syncthreads();

    const int pos_count = s_pos_count;

    // ---- thread 0: emit roi/class/deltas for row k ----
    if (threadIdx.x == 0) {
        float r0 = 0.f, r1 = 0.f, r2 = 0.f, r3 = 0.f;
        float cls = 0.f;
        float d0 = 0.f, d1 = 0.f, d2 = 0.f, d3 = 0.f;
        if (k < PPOS) {
            if (k < pos_count) {
                int idx = s_pos_idx[k];
                const float* p = props + (img * NPROP + idx) * 4;
                r0 = p[0]; r1 = p[1]; r2 = p[2]; r3 = p[3];
                int bg = g_best[img][idx];
                cls = (float)ids[img * MAXGT + bg];
                const float* g = gtb + (img * MAXGT + bg) * 4;
                float gy1 = g[0], gx1 = g[1], gy2 = g[2], gx2 = g[3];
                float h  = fmaxf(__fsub_rn(r2, r0), EPSF);
                float w  = fmaxf(__fsub_rn(r3, r1), EPSF);
                float cy = __fadd_rn(r0, __fmul_rn(0.5f, h));
                float cx = __fadd_rn(r1, __fmul_rn(0.5f, w));
                float gh = fmaxf(__fsub_rn(gy2, gy1), EPSF);
                float gw = fmaxf(__fsub_rn(gx2, gx1), EPSF);
                float gcy = __fadd_rn(gy1, __fmul_rn(0.5f, gh));
                float gcx = __fadd_rn(gx1, __fmul_rn(0.5f, gw));
                d0 = __fmul_rn(__fdiv_rn(__fsub_rn(gcy, cy), h), RCP_01);
                d1 = __fmul_rn(__fdiv_rn(__fsub_rn(gcx, cx), w), RCP_01);
                d2 = __fmul_rn(logf(__fdiv_rn(gh, h)), RCP_02);
                d3 = __fmul_rn(logf(__fdiv_rn(gw, w)), RCP_02);
            }
        } else {
            int j = k - PPOS;
            if (j < s_neg_count) {
                int idx = s_neg_idx[j];
                const float* p = props + (img * NPROP + idx) * 4;
                r0 = p[0]; r1 = p[1]; r2 = p[2]; r3 = p[3];
            }
        }
        int row = img * NROIS + k;
        float* rois = out + OFF_ROIS + row * 4;
        rois[0] = r0; rois[1] = r1; rois[2] = r2; rois[3] = r3;
        out[OFF_CLS + row] = cls;
        float* del = out + OFF_DEL + row * 4;
        del[0] = d0; del[1] = d1; del[2] = d2; del[3] = d3;
    }

    // ---- all threads: mask pixel t of row k ----
    const int t = threadIdx.x;  // 0..783
    float val = 0.0f;
    if (k < pos_count) {
        const int fmt = s_fmt;
        const int idx = s_pos_idx[k];
        const int g   = g_best[img][idx];
        const float* p = props + (img * NPROP + idx) * 4;
        float y1 = p[0], x1 = p[1], y2 = p[2], x2 = p[3];
        int i = t / MW, j = t % MW;
        float iy = __fmul_rn((float)i, RCP_27);
        float ix = __fmul_rn((float)j, RCP_27);
        float ys = __fmul_rn(__fadd_rn(y1, __fmul_rn(iy, __fsub_rn(y2, y1))), (float)(HH - 1));
        float xs = __fmul_rn(__fadd_rn(x1, __fmul_rn(ix, __fsub_rn(x2, x1))), (float)(WW - 1));
        float y0f = floorf(ys), x0f = floorf(xs);
        float ly = __fsub_rn(ys, y0f);
        float lx = __fsub_rn(xs, x0f);
        int y0  = min(max((int)y0f, 0), HH - 1);
        int y1i = min(y0 + 1, HH - 1);
        int x0  = min(max((int)x0f, 0), WW - 1);
        int x1i = min(x0 + 1, WW - 1);
        int rowbase0 = (img * HH + y0)  * WW;
        int rowbase1 = (img * HH + y1i) * WW;
        float v00 = mask_at(masks, fmt, (rowbase0 + x0)  * MAXGT + g);
        float v01 = mask_at(masks, fmt, (rowbase0 + x1i) * MAXGT + g);
        float v10 = mask_at(masks, fmt, (rowbase1 + x0)  * MAXGT + g);
        float v11 = mask_at(masks, fmt, (rowbase1 + x1i) * MAXGT + g);
        float omlx = __fsub_rn(1.0f, lx);
        float omly = __fsub_rn(1.0f, ly);
        float top = __fadd_rn(__fmul_rn(v00, omlx), __fmul_rn(v01, lx));
        float bot = __fadd_rn(__fmul_rn(v10, omlx), __fmul_rn(v11, lx));
        val = rintf(__fadd_rn(__fmul_rn(top, omly), __fmul_rn(bot, ly)));  // half-to-even
    }
    out[OFF_MSK + (img * NROIS + k) * (MH * MW) + t] = val;
}

// ---------------- launch ----------------
extern "C" void kernel_launch(void* const* d_in, const int* in_sizes, int n_in,
                              void* d_out, int out_size) {
    const float* props = (const float*)d_in[0];
    const int*   ids   = (const int*)  d_in[1];
    const float* gtb   = (const float*)d_in[2];
    const void*  masks = d_in[3];
    float* out = (float*)d_out;

    k_iou<<<dim3(NPROP / 8, NIMG), 256>>>(props, ids, gtb);
    k_emit_masks<<<dim3(NROIS, NIMG), MH * MW>>>(props, ids, gtb, masks, out);
}

// round 9
// speedup vs baseline: 1.3009x; 1.3009x over previous
#include <cuda_runtime.h>
#include <cuda_bf16.h>
#include <math.h>

#define NIMG   4
#define NPROP  2000
#define MAXGT  64
#define HH     512
#define WW     512
#define PPOS   66
#define NNEG   134
#define NROIS  200
#define MH     28
#define MW     28
#define EPSF   1e-8f
#define NWORDS (NPROP / 4)        // 500 packed flag words per image

// Output layout (float32, concatenated flattened tuple):
//   rois    [4][200][4]     @ 0      (3200)
//   class   [4][200]        @ 3200   (800)
//   deltas  [4][200][4]     @ 4000   (3200)
//   masks   [4][200][28][28]@ 7200   (627200)
#define OFF_ROIS  0
#define OFF_CLS   3200
#define OFF_DEL   4000
#define OFF_MSK   7200

// XLA rewrites x / const into x * (1/const) (algebraic simplifier).
#define RCP_033  (1.0f / 0.33f)   // 66*r rounds to exactly 200.0f
#define RCP_01   (1.0f / 0.1f)    // exactly 10.0f
#define RCP_02   (1.0f / 0.2f)    // exactly 5.0f
#define RCP_27   (1.0f / 27.0f)

// ---------------- device scratch (no allocations allowed) ----------------
__device__ int            g_best[NIMG][NPROP];
__device__ unsigned char  g_posf[NIMG][NPROP];   // 0/1 bytes
__device__ unsigned char  g_negf[NIMG][NPROP];
__device__ int            g_mask_fmt;            // 0=u8, 1=i32, 2=f32, 3=bf16

__device__ __forceinline__ float mask_at(const void* m, int fmt, int idx) {
    switch (fmt) {
        case 0:  return (float)__ldg((const unsigned char*)m + idx);
        case 1:  return (float)__ldg((const int*)m + idx);
        case 3: {
            unsigned short u = __ldg((const unsigned short*)m + idx);
            __nv_bfloat16 v;
            *(unsigned short*)&v = u;
            return __bfloat162float(v);
        }
        default: return __ldg((const float*)m + idx);
    }
}

// ---------------- IoU / flags: one WARP per proposal ----------------
// Block (0, img=0) warp 0 additionally probes the mask dtype with uint4
// loads (8 x 16B per lane over the first 4KB) and publishes g_mask_fmt.
__global__ void __launch_bounds__(256)
k_iou(const float* __restrict__ props,
      const int*   __restrict__ ids,
      const float* __restrict__ gtb,
      const uint4* __restrict__ masks_raw) {
    const int img  = blockIdx.y;
    const int wid  = threadIdx.x >> 5;
    const int lane = threadIdx.x & 31;
    const int prop = blockIdx.x * 8 + wid;   // 250*8 = 2000

    __shared__ float4 sgt[MAXGT];
    __shared__ int    sfl[MAXGT];   // bit0: gt_valid, bit1: crowd
    if (threadIdx.x < MAXGT) {
        const float* g = gtb + (img * MAXGT + threadIdx.x) * 4;
        float4 b; b.x = g[0]; b.y = g[1]; b.z = g[2]; b.w = g[3];
        sgt[threadIdx.x] = b;
        int id = ids[img * MAXGT + threadIdx.x];
        bool bv = (b.x != 0.f) || (b.y != 0.f) || (b.z != 0.f) || (b.w != 0.f);
        sfl[threadIdx.x] = ((bv && id > 0) ? 1 : 0) | ((bv && id < 0) ? 2 : 0);
    }
    __syncthreads();

    const float4 p = *(const float4*)(props + (img * NPROP + prop) * 4);
    const float py1 = p.x, px1 = p.y, py2 = p.z, px2 = p.w;
    const bool prop_valid = (py1 != 0.f) || (px1 != 0.f) || (py2 != 0.f) || (px2 != 0.f);
    const float a1 = __fmul_rn(__fsub_rn(py2, py1), __fsub_rn(px2, px1));

    float best = -INFINITY; int bi = 0;
    float crowd_max = -1.0f;
    #pragma unroll
    for (int t = 0; t < 2; ++t) {
        const int j = lane + 32 * t;
        float4 g = sgt[j];
        int fl = sfl[j];
        float ih = fmaxf(__fsub_rn(fminf(py2, g.z), fmaxf(py1, g.x)), 0.0f);
        float iw = fmaxf(__fsub_rn(fminf(px2, g.w), fmaxf(px1, g.y)), 0.0f);
        float inter = __fmul_rn(ih, iw);
        float a2 = __fmul_rn(__fsub_rn(g.z, g.x), __fsub_rn(g.w, g.y));
        float denom = __fadd_rn(__fsub_rn(__fadd_rn(a1, a2), inter), EPSF);
        float iou = __fdiv_rn(inter, denom);
        float ov = (fl & 1) ? iou : -1.0f;
        if (ov > best) { best = ov; bi = j; }   // j < j+32: first-max kept
        float cv = (fl & 2) ? iou : -1.0f;
        crowd_max = fmaxf(crowd_max, cv);
    }

    #pragma unroll
    for (int off = 16; off > 0; off >>= 1) {
        float ob = __shfl_xor_sync(0xFFFFFFFFu, best, off);
        int   oi = __shfl_xor_sync(0xFFFFFFFFu, bi, off);
        float oc = __shfl_xor_sync(0xFFFFFFFFu, crowd_max, off);
        if (ob > best || (ob == best && oi < bi)) { best = ob; bi = oi; }
        crowd_max = fmaxf(crowd_max, oc);
    }

    if (lane == 0) {
        bool pos = (best >= 0.5f) && prop_valid;
        bool neg = (best < 0.5f) && (crowd_max < 0.001f) && prop_valid && !pos;
        g_best[img][prop] = bi;
        g_posf[img][prop] = pos ? 1 : 0;
        g_negf[img][prop] = neg ? 1 : 0;
    }

    // ---- one-time mask dtype probe (block (0,0), warp 0) ----
    // Mask holds only 0/1 values; byte patterns discriminate the dtype:
    //   any byte > 1              -> f32 or bf16
    //     byte at p%4==1 nonzero  -> bf16
    //   else byte==1 at p%4!=0    -> uint8
    //   else                      -> int32
    if (blockIdx.x == 0 && img == 0 && wid == 0) {
        int a = 0, b = 0, c = 0;
        #pragma unroll
        for (int t = 0; t < 8; ++t) {           // 8*32 uint4 = 4096 bytes
            uint4 v = __ldg(masks_raw + t * 32 + lane);
            unsigned ws[4] = {v.x, v.y, v.z, v.w};
            #pragma unroll
            for (int q = 0; q < 4; ++q) {
                unsigned w = ws[q];
                unsigned b0 = w & 0xFFu, b1 = (w >> 8) & 0xFFu;
                unsigned b2 = (w >> 16) & 0xFFu, b3 = (w >> 24) & 0xFFu;
                if (b0 > 1u || b1 > 1u || b2 > 1u || b3 > 1u) a = 1;
                if (b1 != 0u) b = 1;
                if (b1 == 1u || b2 == 1u || b3 == 1u) c = 1;
            }
        }
        unsigned am = __ballot_sync(0xFFFFFFFFu, a);
        unsigned bm = __ballot_sync(0xFFFFFFFFu, b);
        unsigned cm = __ballot_sync(0xFFFFFFFFu, c);
        if (lane == 0) {
            int fmt;
            if (am) fmt = bm ? 3 : 2;
            else    fmt = cm ? 0 : 1;
            g_mask_fmt = fmt;
        }
    }
}

// ---- fused: per-block selection scan + roi/cls/delta emit + mask row ----
// Grid (NROIS, NIMG), 784 threads. Warp 0 redoes a (cheap, specialized)
// stable first-k compaction: pos-row blocks scan pos flags only; neg-row
// blocks popc-count pos and rank-scan neg. Then thread 0 emits the roi row
// and all threads produce the 28x28 mask row.
__global__ void __launch_bounds__(784, 2)
k_emit_masks(const float* __restrict__ props,
             const int*   __restrict__ ids,
             const float* __restrict__ gtb,
             const void*  __restrict__ masks,
             float* __restrict__ out) {
    const int img = blockIdx.y;
    const int k   = blockIdx.x;      // 0..199 (roi row / mask row)
    const bool is_pos_row = (k < PPOS);

    __shared__ int s_idx[NNEG];      // pos rows use [0..PPOS), neg rows [0..NNEG)
    __shared__ int s_pos_count, s_neg_count;

    if (threadIdx.x < 32) {
        const int lane = threadIdx.x;
        const unsigned* pw = (const unsigned*)&g_posf[img][0];  // 500 words
        const unsigned* nw = (const unsigned*)&g_negf[img][0];
        const int base = lane * 16;
        const unsigned* rankw = is_pos_row ? pw : nw;  // array we rank-scan

        int cr = 0;          // rank-array count in my chunk
        int cp_only = 0;     // pos count (neg rows need total only)
        #pragma unroll
        for (int t = 0; t < 16; ++t) {
            const int widx = base + t;
            if (widx < NWORDS) {
                cr += __popc(__ldg(rankw + widx));
                if (!is_pos_row) cp_only += __popc(__ldg(pw + widx));
            }
        }
        // inclusive prefix over the rank array
        int rinc = cr;
        #pragma unroll
        for (int off = 1; off < 32; off <<= 1) {
            int up = __shfl_up_sync(0xFFFFFFFFu, rinc, off);
            if (lane >= off) rinc += up;
        }
        const int rtot = __shfl_sync(0xFFFFFFFFu, rinc, 31);
        const int cap  = is_pos_row ? PPOS : NNEG;
        int rr = rinc - cr;
        if (cr > 0 && rr < cap) {
            for (int t = 0; t < 16; ++t) {
                const int widx = base + t;
                unsigned w = (widx < NWORDS) ? __ldg(rankw + widx) : 0u;
                if (!w) continue;
                #pragma unroll
                for (int b = 0; b < 4; ++b)
                    if ((w >> (8 * b)) & 1u) {
                        if (rr < cap) s_idx[rr] = widx * 4 + b;
                        rr++;
                    }
            }
        }
        if (is_pos_row) {
            if (lane == 0)
                s_pos_count = rtot < PPOS ? rtot : PPOS;
        } else {
            // reduce pos total across lanes
            int pt = cp_only;
            #pragma unroll
            for (int off = 16; off > 0; off >>= 1)
                pt += __shfl_xor_sync(0xFFFFFFFFu, pt, off);
            if (lane == 0) {
                int pos_count = pt < PPOS ? pt : PPOS;
                int neg_target = (int)(__fmul_rn((float)pos_count, RCP_033)) - pos_count;
                int avail = rtot < NNEG ? rtot : NNEG;
                s_pos_count = pos_count;
                s_neg_count = neg_target < 0 ? 0 : (neg_target < avail ? neg_target : avail);
            }
        }
    }
    __syncthreads();

    const int pos_count = s_pos_count;

    // ---- thread 0: emit roi/class/deltas for row k ----
    if (threadIdx.x == 0) {
        float r0 = 0.f, r1 = 0.f, r2 = 0.f, r3 = 0.f;
        float cls = 0.f;
        float d0 = 0.f, d1 = 0.f, d2 = 0.f, d3 = 0.f;
        if (is_pos_row) {
            if (k < pos_count) {
                int idx = s_idx[k];
                const float* p = props + (img * NPROP + idx) * 4;
                r0 = p[0]; r1 = p[1]; r2 = p[2]; r3 = p[3];
                int bg = g_best[img][idx];
                cls = (float)ids[img * MAXGT + bg];
                const float* g = gtb + (img * MAXGT + bg) * 4;
                float gy1 = g[0], gx1 = g[1], gy2 = g[2], gx2 = g[3];
                float h  = fmaxf(__fsub_rn(r2, r0), EPSF);
                float w  = fmaxf(__fsub_rn(r3, r1), EPSF);
                float cy = __fadd_rn(r0, __fmul_rn(0.5f, h));
                float cx = __fadd_rn(r1, __fmul_rn(0.5f, w));
                float gh = fmaxf(__fsub_rn(gy2, gy1), EPSF);
                float gw = fmaxf(__fsub_rn(gx2, gx1), EPSF);
                float gcy = __fadd_rn(gy1, __fmul_rn(0.5f, gh));
                float gcx = __fadd_rn(gx1, __fmul_rn(0.5f, gw));
                d0 = __fmul_rn(__fdiv_rn(__fsub_rn(gcy, cy), h), RCP_01);
                d1 = __fmul_rn(__fdiv_rn(__fsub_rn(gcx, cx), w), RCP_01);
                d2 = __fmul_rn(logf(__fdiv_rn(gh, h)), RCP_02);
                d3 = __fmul_rn(logf(__fdiv_rn(gw, w)), RCP_02);
            }
        } else {
            int j = k - PPOS;
            if (j < s_neg_count) {
                int idx = s_idx[j];
                const float* p = props + (img * NPROP + idx) * 4;
                r0 = p[0]; r1 = p[1]; r2 = p[2]; r3 = p[3];
            }
        }
        int row = img * NROIS + k;
        float* rois = out + OFF_ROIS + row * 4;
        rois[0] = r0; rois[1] = r1; rois[2] = r2; rois[3] = r3;
        out[OFF_CLS + row] = cls;
        float* del = out + OFF_DEL + row * 4;
        del[0] = d0; del[1] = d1; del[2] = d2; del[3] = d3;
    }

    // ---- all threads: mask pixel t of row k (k >= pos_count -> zeros) ----
    const int t = threadIdx.x;  // 0..783
    float val = 0.0f;
    if (is_pos_row && k < pos_count) {
        const int fmt = g_mask_fmt;
        const int idx = s_idx[k];
        const int g   = g_best[img][idx];
        const float* p = props + (img * NPROP + idx) * 4;
        float y1 = p[0], x1 = p[1], y2 = p[2], x2 = p[3];
        int i = t / MW, j = t % MW;
        float iy = __fmul_rn((float)i, RCP_27);
        float ix = __fmul_rn((float)j, RCP_27);
        float ys = __fmul_rn(__fadd_rn(y1, __fmul_rn(iy, __fsub_rn(y2, y1))), (float)(HH - 1));
        float xs = __fmul_rn(__fadd_rn(x1, __fmul_rn(ix, __fsub_rn(x2, x1))), (float)(WW - 1));
        float y0f = floorf(ys), x0f = floorf(xs);
        float ly = __fsub_rn(ys, y0f);
        float lx = __fsub_rn(xs, x0f);
        int y0  = min(max((int)y0f, 0), HH - 1);
        int y1i = min(y0 + 1, HH - 1);
        int x0  = min(max((int)x0f, 0), WW - 1);
        int x1i = min(x0 + 1, WW - 1);
        int rowbase0 = (img * HH + y0)  * WW;
        int rowbase1 = (img * HH + y1i) * WW;
        float v00 = mask_at(masks, fmt, (rowbase0 + x0)  * MAXGT + g);
        float v01 = mask_at(masks, fmt, (rowbase0 + x1i) * MAXGT + g);
        float v10 = mask_at(masks, fmt, (rowbase1 + x0)  * MAXGT + g);
        float v11 = mask_at(masks, fmt, (rowbase1 + x1i) * MAXGT + g);
        float omlx = __fsub_rn(1.0f, lx);
        float omly = __fsub_rn(1.0f, ly);
        float top = __fadd_rn(__fmul_rn(v00, omlx), __fmul_rn(v01, lx));
        float bot = __fadd_rn(__fmul_rn(v10, omlx), __fmul_rn(v11, lx));
        val = rintf(__fadd_rn(__fmul_rn(top, omly), __fmul_rn(bot, ly)));  // half-to-even
    }
    out[OFF_MSK + (img * NROIS + k) * (MH * MW) + t] = val;
}

// ---------------- launch ----------------
extern "C" void kernel_launch(void* const* d_in, const int* in_sizes, int n_in,
                              void* d_out, int out_size) {
    const float* props = (const float*)d_in[0];
    const int*   ids   = (const int*)  d_in[1];
    const float* gtb   = (const float*)d_in[2];
    const void*  masks = d_in[3];
    float* out = (float*)d_out;

    k_iou<<<dim3(NPROP / 8, NIMG), 256>>>(props, ids, gtb, (const uint4*)masks);
    k_emit_masks<<<dim3(NROIS, NIMG), MH * MW>>>(props, ids, gtb, masks, out);
}

// round 10
// speedup vs baseline: 1.5414x; 1.1849x over previous
#include <cuda_runtime.h>
#include <cuda_bf16.h>
#include <math.h>

#define NIMG   4
#define NPROP  2000
#define MAXGT  64
#define HH     512
#define WW     512
#define PPOS   66
#define NNEG   134
#define NROIS  200
#define MH     28
#define MW     28
#define EPSF   1e-8f
#define NWORDS (NPROP / 4)        // 500 packed flag words per image
#define NQ4    (NIMG * NROIS * (MH * MW / 4))   // 156800 float4 outputs

// Output layout (float32, concatenated flattened tuple):
//   rois    [4][200][4]     @ 0      (3200)
//   class   [4][200]        @ 3200   (800)
//   deltas  [4][200][4]     @ 4000   (3200)
//   masks   [4][200][28][28]@ 7200   (627200)
#define OFF_ROIS  0
#define OFF_CLS   3200
#define OFF_DEL   4000
#define OFF_MSK   7200

// XLA rewrites x / const into x * (1/const) (algebraic simplifier).
#define RCP_033  (1.0f / 0.33f)   // 66*r rounds to exactly 200.0f
#define RCP_01   (1.0f / 0.1f)    // exactly 10.0f
#define RCP_02   (1.0f / 0.2f)    // exactly 5.0f
#define RCP_27   (1.0f / 27.0f)

// ---------------- device scratch (no allocations allowed) ----------------
__device__ int            g_best[NIMG][NPROP];
__device__ unsigned char  g_posf[NIMG][NPROP];   // 0/1 bytes
__device__ unsigned char  g_negf[NIMG][NPROP];
__device__ int            g_pos_idx[NIMG][PPOS];
__device__ int            g_pos_count[NIMG];
__device__ int            g_mask_fmt;            // 0=u8, 1=i32, 2=f32, 3=bf16

__device__ __forceinline__ float mask_at(const void* m, int fmt, int idx) {
    switch (fmt) {
        case 0:  return (float)__ldg((const unsigned char*)m + idx);
        case 1:  return (float)__ldg((const int*)m + idx);
        case 3: {
            unsigned short u = __ldg((const unsigned short*)m + idx);
            __nv_bfloat16 v;
            *(unsigned short*)&v = u;
            return __bfloat162float(v);
        }
        default: return __ldg((const float*)m + idx);
    }
}

// ---------------- IoU / flags: one WARP per proposal ----------------
// Block (0, img=0) warp 0 additionally probes the mask dtype with uint4
// loads (8 x 16B per lane over the first 4KB) and publishes g_mask_fmt.
__global__ void __launch_bounds__(256)
k_iou(const float* __restrict__ props,
      const int*   __restrict__ ids,
      const float* __restrict__ gtb,
      const uint4* __restrict__ masks_raw) {
    const int img  = blockIdx.y;
    const int wid  = threadIdx.x >> 5;
    const int lane = threadIdx.x & 31;
    const int prop = blockIdx.x * 8 + wid;   // 250*8 = 2000

    __shared__ float4 sgt[MAXGT];
    __shared__ int    sfl[MAXGT];   // bit0: gt_valid, bit1: crowd
    if (threadIdx.x < MAXGT) {
        const float* g = gtb + (img * MAXGT + threadIdx.x) * 4;
        float4 b; b.x = g[0]; b.y = g[1]; b.z = g[2]; b.w = g[3];
        sgt[threadIdx.x] = b;
        int id = ids[img * MAXGT + threadIdx.x];
        bool bv = (b.x != 0.f) || (b.y != 0.f) || (b.z != 0.f) || (b.w != 0.f);
        sfl[threadIdx.x] = ((bv && id > 0) ? 1 : 0) | ((bv && id < 0) ? 2 : 0);
    }
    __syncthreads();

    const float4 p = *(const float4*)(props + (img * NPROP + prop) * 4);
    const float py1 = p.x, px1 = p.y, py2 = p.z, px2 = p.w;
    const bool prop_valid = (py1 != 0.f) || (px1 != 0.f) || (py2 != 0.f) || (px2 != 0.f);
    const float a1 = __fmul_rn(__fsub_rn(py2, py1), __fsub_rn(px2, px1));

    float best = -INFINITY; int bi = 0;
    float crowd_max = -1.0f;
    #pragma unroll
    for (int t = 0; t < 2; ++t) {
        const int j = lane + 32 * t;
        float4 g = sgt[j];
        int fl = sfl[j];
        float ih = fmaxf(__fsub_rn(fminf(py2, g.z), fmaxf(py1, g.x)), 0.0f);
        float iw = fmaxf(__fsub_rn(fminf(px2, g.w), fmaxf(px1, g.y)), 0.0f);
        float inter = __fmul_rn(ih, iw);
        float a2 = __fmul_rn(__fsub_rn(g.z, g.x), __fsub_rn(g.w, g.y));
        float denom = __fadd_rn(__fsub_rn(__fadd_rn(a1, a2), inter), EPSF);
        float iou = __fdiv_rn(inter, denom);
        float ov = (fl & 1) ? iou : -1.0f;
        if (ov > best) { best = ov; bi = j; }   // j < j+32: first-max kept
        float cv = (fl & 2) ? iou : -1.0f;
        crowd_max = fmaxf(crowd_max, cv);
    }

    #pragma unroll
    for (int off = 16; off > 0; off >>= 1) {
        float ob = __shfl_xor_sync(0xFFFFFFFFu, best, off);
        int   oi = __shfl_xor_sync(0xFFFFFFFFu, bi, off);
        float oc = __shfl_xor_sync(0xFFFFFFFFu, crowd_max, off);
        if (ob > best || (ob == best && oi < bi)) { best = ob; bi = oi; }
        crowd_max = fmaxf(crowd_max, oc);
    }

    if (lane == 0) {
        bool pos = (best >= 0.5f) && prop_valid;
        bool neg = (best < 0.5f) && (crowd_max < 0.001f) && prop_valid && !pos;
        g_best[img][prop] = bi;
        g_posf[img][prop] = pos ? 1 : 0;
        g_negf[img][prop] = neg ? 1 : 0;
    }

    // ---- one-time mask dtype probe (block (0,0), warp 0) ----
    //   any byte > 1              -> f32 or bf16
    //     byte at p%4==1 nonzero  -> bf16
    //   else byte==1 at p%4!=0    -> uint8
    //   else                      -> int32
    if (blockIdx.x == 0 && img == 0 && wid == 0) {
        int a = 0, b = 0, c = 0;
        #pragma unroll
        for (int t = 0; t < 8; ++t) {           // 8*32 uint4 = 4096 bytes
            uint4 v = __ldg(masks_raw + t * 32 + lane);
            unsigned ws[4] = {v.x, v.y, v.z, v.w};
            #pragma unroll
            for (int q = 0; q < 4; ++q) {
                unsigned w = ws[q];
                unsigned b0 = w & 0xFFu, b1 = (w >> 8) & 0xFFu;
                unsigned b2 = (w >> 16) & 0xFFu, b3 = (w >> 24) & 0xFFu;
                if (b0 > 1u || b1 > 1u || b2 > 1u || b3 > 1u) a = 1;
                if (b1 != 0u) b = 1;
                if (b1 == 1u || b2 == 1u || b3 == 1u) c = 1;
            }
        }
        unsigned am = __ballot_sync(0xFFFFFFFFu, a);
        unsigned bm = __ballot_sync(0xFFFFFFFFu, b);
        unsigned cm = __ballot_sync(0xFFFFFFFFu, c);
        if (lane == 0) {
            int fmt;
            if (am) fmt = bm ? 3 : 2;
            else    fmt = cm ? 0 : 1;
            g_mask_fmt = fmt;
        }
    }
}

// ---- stable first-k chunk compaction (warp-collective) ----
// Lane owns 16 contiguous words (64 proposals): popc-count, shuffle prefix,
// rewalk writing ranked indices into s_out. Returns the total flag count.
__device__ __forceinline__ int chunk_scan(const unsigned* __restrict__ w,
                                          int lane, int cap, int* s_out) {
    const int base = lane * 16;
    int c = 0;
    #pragma unroll
    for (int t = 0; t < 16; ++t) {
        const int wi = base + t;
        if (wi < NWORDS) c += __popc(__ldg(w + wi));
    }
    int inc = c;
    #pragma unroll
    for (int off = 1; off < 32; off <<= 1) {
        int up = __shfl_up_sync(0xFFFFFFFFu, inc, off);
        if (lane >= off) inc += up;
    }
    const int tot = __shfl_sync(0xFFFFFFFFu, inc, 31);
    int r = inc - c;
    if (c > 0 && r < cap) {
        for (int t = 0; t < 16; ++t) {
            const int wi = base + t;
            unsigned x = (wi < NWORDS) ? __ldg(w + wi) : 0u;
            if (!x) continue;
            #pragma unroll
            for (int b = 0; b < 4; ++b)
                if ((x >> (8 * b)) & 1u) {
                    if (r < cap) s_out[r] = wi * 4 + b;
                    r++;
                }
        }
    }
    return tot;
}

// ------- selection (2 warps in parallel) + rois/class/deltas emit -------
__global__ void __launch_bounds__(256)
k_select_emit(const float* __restrict__ props,
              const int*   __restrict__ ids,
              const float* __restrict__ gtb,
              float* __restrict__ out) {
    const int img = blockIdx.x;
    __shared__ int s_pos_idx[PPOS];
    __shared__ int s_neg_idx[NNEG];
    __shared__ int s_ptot, s_ntot;

    if (threadIdx.x < 32) {
        int ptot = chunk_scan((const unsigned*)&g_posf[img][0], threadIdx.x,
                              PPOS, s_pos_idx);
        if (threadIdx.x == 0) s_ptot = ptot;
    } else if (threadIdx.x < 64) {
        int ntot = chunk_scan((const unsigned*)&g_negf[img][0], threadIdx.x - 32,
                              NNEG, s_neg_idx);
        if (threadIdx.x == 32) s_ntot = ntot;
    }
    __syncthreads();

    const int pos_count = s_ptot < PPOS ? s_ptot : PPOS;
    // Publish for the mask kernel.
    if (threadIdx.x < PPOS) g_pos_idx[img][threadIdx.x] = s_pos_idx[threadIdx.x];
    if (threadIdx.x == 0)   g_pos_count[img] = pos_count;

    const int k = threadIdx.x;   // 0..199 emit; others exit
    if (k >= NROIS) return;

    float r0 = 0.f, r1 = 0.f, r2 = 0.f, r3 = 0.f;
    float cls = 0.f;
    float d0 = 0.f, d1 = 0.f, d2 = 0.f, d3 = 0.f;

    if (k < PPOS) {
        if (k < pos_count) {
            int idx = s_pos_idx[k];
            const float* p = props + (img * NPROP + idx) * 4;
            r0 = p[0]; r1 = p[1]; r2 = p[2]; r3 = p[3];
            int bg = g_best[img][idx];
            cls = (float)ids[img * MAXGT + bg];
            const float* g = gtb + (img * MAXGT + bg) * 4;
            float gy1 = g[0], gx1 = g[1], gy2 = g[2], gx2 = g[3];
            float h  = fmaxf(__fsub_rn(r2, r0), EPSF);
            float w  = fmaxf(__fsub_rn(r3, r1), EPSF);
            float cy = __fadd_rn(r0, __fmul_rn(0.5f, h));
            float cx = __fadd_rn(r1, __fmul_rn(0.5f, w));
            float gh = fmaxf(__fsub_rn(gy2, gy1), EPSF);
            float gw = fmaxf(__fsub_rn(gx2, gx1), EPSF);
            float gcy = __fadd_rn(gy1, __fmul_rn(0.5f, gh));
            float gcx = __fadd_rn(gx1, __fmul_rn(0.5f, gw));
            d0 = __fmul_rn(__fdiv_rn(__fsub_rn(gcy, cy), h), RCP_01);
            d1 = __fmul_rn(__fdiv_rn(__fsub_rn(gcx, cx), w), RCP_01);
            d2 = __fmul_rn(logf(__fdiv_rn(gh, h)), RCP_02);
            d3 = __fmul_rn(logf(__fdiv_rn(gw, w)), RCP_02);
        }
    } else {
        // neg_count computed redundantly per thread (cheap, avoids 2nd sync)
        int neg_target = (int)(__fmul_rn((float)pos_count, RCP_033)) - pos_count;
        int avail = s_ntot < NNEG ? s_ntot : NNEG;
        int neg_count = neg_target < 0 ? 0 : (neg_target < avail ? neg_target : avail);
        int j = k - PPOS;
        if (j < neg_count) {
            int idx = s_neg_idx[j];
            const float* p = props + (img * NPROP + idx) * 4;
            r0 = p[0]; r1 = p[1]; r2 = p[2]; r3 = p[3];
        }
    }
    int row = img * NROIS + k;
    float* rois = out + OFF_ROIS + row * 4;
    rois[0] = r0; rois[1] = r1; rois[2] = r2; rois[3] = r3;
    out[OFF_CLS + row] = cls;
    float* del = out + OFF_DEL + row * 4;
    del[0] = d0; del[1] = d1; del[2] = d2; del[3] = d3;
}

// ---------------- mask crop-resize: one thread per float4 ----------------
// 4 consecutive pixels of one roi row per thread: metadata loaded once,
// 16 independent mask gathers in flight, one 128-bit store. No smem, no
// sync, no prologue — pure gather streaming for maximum DRAM queue depth.
__global__ void __launch_bounds__(256)
k_masks(const float* __restrict__ props,
        const void*  __restrict__ masks,
        float* __restrict__ out) {
    const int q = blockIdx.x * 256 + threadIdx.x;
    if (q >= NQ4) return;
    const int img = q / (NROIS * 196);
    const int rem = q % (NROIS * 196);
    const int k   = rem / 196;
    const int t4  = (rem % 196) * 4;

    float4 res = make_float4(0.f, 0.f, 0.f, 0.f);
    if (k < __ldg(&g_pos_count[img])) {      // only pos rows have masks
        const int fmt = g_mask_fmt;
        const int idx = __ldg(&g_pos_idx[img][k]);
        const int g   = __ldg(&g_best[img][idx]);
        const float4 pb = __ldg((const float4*)(props + (img * NPROP + idx) * 4));
        const float y1 = pb.x, x1 = pb.y, y2 = pb.z, x2 = pb.w;
        float v[4];
        #pragma unroll
        for (int u = 0; u < 4; ++u) {
            const int t = t4 + u;
            const int i = t / MW, j = t % MW;
            float iy = __fmul_rn((float)i, RCP_27);
            float ix = __fmul_rn((float)j, RCP_27);
            float ys = __fmul_rn(__fadd_rn(y1, __fmul_rn(iy, __fsub_rn(y2, y1))), (float)(HH - 1));
            float xs = __fmul_rn(__fadd_rn(x1, __fmul_rn(ix, __fsub_rn(x2, x1))), (float)(WW - 1));
            float y0f = floorf(ys), x0f = floorf(xs);
            float ly = __fsub_rn(ys, y0f);
            float lx = __fsub_rn(xs, x0f);
            int y0  = min(max((int)y0f, 0), HH - 1);
            int y1i = min(y0 + 1, HH - 1);
            int x0  = min(max((int)x0f, 0), WW - 1);
            int x1i = min(x0 + 1, WW - 1);
            int rowbase0 = (img * HH + y0)  * WW;
            int rowbase1 = (img * HH + y1i) * WW;
            float v00 = mask_at(masks, fmt, (rowbase0 + x0)  * MAXGT + g);
            float v01 = mask_at(masks, fmt, (rowbase0 + x1i) * MAXGT + g);
            float v10 = mask_at(masks, fmt, (rowbase1 + x0)  * MAXGT + g);
            float v11 = mask_at(masks, fmt, (rowbase1 + x1i) * MAXGT + g);
            float omlx = __fsub_rn(1.0f, lx);
            float omly = __fsub_rn(1.0f, ly);
            float top = __fadd_rn(__fmul_rn(v00, omlx), __fmul_rn(v01, lx));
            float bot = __fadd_rn(__fmul_rn(v10, omlx), __fmul_rn(v11, lx));
            v[u] = rintf(__fadd_rn(__fmul_rn(top, omly), __fmul_rn(bot, ly)));  // half-to-even
        }
        res = make_float4(v[0], v[1], v[2], v[3]);
    }
    *(float4*)(out + OFF_MSK + (img * NROIS + k) * (MH * MW) + t4) = res;
}

// ---------------- launch ----------------
extern "C" void kernel_launch(void* const* d_in, const int* in_sizes, int n_in,
                              void* d_out, int out_size) {
    const float* props = (const float*)d_in[0];
    const int*   ids   = (const int*)  d_in[1];
    const float* gtb   = (const float*)d_in[2];
    const void*  masks = d_in[3];
    float* out = (float*)d_out;

    k_iou<<<dim3(NPROP / 8, NIMG), 256>>>(props, ids, gtb, (const uint4*)masks);
    k_select_emit<<<NIMG, 256>>>(props, ids, gtb, out);
    k_masks<<<(NQ4 + 255) / 256, 256>>>(props, masks, out);
}